// round 1
// baseline (speedup 1.0000x reference)
#include <cuda_runtime.h>
#include <math_constants.h>

#define N 512
#define D 128
#define TI 16              // anchors per block in the distance kernel
#define MARGIN 0.3f

// Scratch (no allocations allowed in kernel_launch)
__device__ float g_dist[N * N];
__device__ double g_sum;
__device__ unsigned long long g_cnt;

// ---------------------------------------------------------------------------
// Kernel 1: pairwise Euclidean distances, 16-anchor tile per block.
// Block 0 thread 0 also zeroes the accumulators (ordered before kernel 2).
// ---------------------------------------------------------------------------
__global__ __launch_bounds__(256) void dist_kernel(const float* __restrict__ x) {
    __shared__ float xs[TI][D];   // 8 KB
    const int i0 = blockIdx.x * TI;

    if (blockIdx.x == 0 && threadIdx.x == 0) {
        g_sum = 0.0;
        g_cnt = 0ull;
    }

    for (int t = threadIdx.x; t < TI * D; t += blockDim.x)
        xs[t / D][t % D] = x[i0 * D + t];
    __syncthreads();

    for (int j = threadIdx.x; j < N; j += blockDim.x) {
        const float4* xj = reinterpret_cast<const float4*>(x + j * D);
        float acc[TI];
#pragma unroll
        for (int ii = 0; ii < TI; ii++) acc[ii] = 0.f;

#pragma unroll 4
        for (int c4 = 0; c4 < D / 4; c4++) {
            float4 b = xj[c4];
#pragma unroll
            for (int ii = 0; ii < TI; ii++) {
                float d0 = xs[ii][c4 * 4 + 0] - b.x;
                float d1 = xs[ii][c4 * 4 + 1] - b.y;
                float d2 = xs[ii][c4 * 4 + 2] - b.z;
                float d3 = xs[ii][c4 * 4 + 3] - b.w;
                acc[ii] = fmaf(d0, d0,
                          fmaf(d1, d1,
                          fmaf(d2, d2,
                          fmaf(d3, d3, acc[ii]))));
            }
        }
#pragma unroll
        for (int ii = 0; ii < TI; ii++)
            g_dist[(i0 + ii) * N + j] = sqrtf(acc[ii]);
    }
}

// ---------------------------------------------------------------------------
// Kernel 2: per-anchor triplet hinge sum + positive count.
// Block = anchor i. Each thread owns k-slots {tid, tid+256}; negatives are
// pre-resolved (non-negative slots -> +INF so the hinge never fires).
// ---------------------------------------------------------------------------
__global__ __launch_bounds__(256) void triplet_kernel(const int* __restrict__ labels) {
    __shared__ float drow[N];
    __shared__ int   slbl[N];
    __shared__ float red_s[8];
    __shared__ unsigned red_c[8];

    const int i   = blockIdx.x;
    const int tid = threadIdx.x;

    for (int t = tid; t < N; t += 256) {
        drow[t] = g_dist[i * N + t];
        slbl[t] = labels[t];
    }
    __syncthreads();

    const int li = slbl[i];
    const float nk0 = (slbl[tid]       != li) ? drow[tid]       : CUDART_INF_F;
    const float nk1 = (slbl[tid + 256] != li) ? drow[tid + 256] : CUDART_INF_F;

    float sum = 0.f;
    unsigned cnt = 0;

    for (int j = 0; j < N; j++) {
        // block-uniform predicate: all threads take the same path
        if (slbl[j] == li && j != i) {
            const float apm = drow[j] + MARGIN;
            const float v0 = apm - nk0;
            const float v1 = apm - nk1;
            if (v0 > 0.f) { sum += v0; cnt += (v0 > 1e-16f); }
            if (v1 > 0.f) { sum += v1; cnt += (v1 > 1e-16f); }
        }
    }

    // block reduction
#pragma unroll
    for (int off = 16; off; off >>= 1) {
        sum += __shfl_down_sync(0xffffffffu, sum, off);
        cnt += __shfl_down_sync(0xffffffffu, cnt, off);
    }
    if ((tid & 31) == 0) { red_s[tid >> 5] = sum; red_c[tid >> 5] = cnt; }
    __syncthreads();
    if (tid < 8) {
        sum = red_s[tid];
        cnt = red_c[tid];
#pragma unroll
        for (int off = 4; off; off >>= 1) {
            sum += __shfl_down_sync(0xffu, sum, off);
            cnt += __shfl_down_sync(0xffu, cnt, off);
        }
        if (tid == 0) {
            atomicAdd(&g_sum, (double)sum);
            atomicAdd(&g_cnt, (unsigned long long)cnt);
        }
    }
}

// ---------------------------------------------------------------------------
// Kernel 3: final scalar
// ---------------------------------------------------------------------------
__global__ void finalize_kernel(float* __restrict__ out) {
    out[0] = (float)(g_sum / ((double)g_cnt + 1e-16));
}

extern "C" void kernel_launch(void* const* d_in, const int* in_sizes, int n_in,
                              void* d_out, int out_size) {
    const float* emb    = (const float*)d_in[0];   // [512, 128] fp32
    const int*   labels = (const int*)d_in[1];     // [512] int32
    float*       out    = (float*)d_out;

    dist_kernel<<<N / TI, 256>>>(emb);
    triplet_kernel<<<N, 256>>>(labels);
    finalize_kernel<<<1, 1>>>(out);
}

// round 2
// speedup vs baseline: 2.9894x; 2.9894x over previous
#include <cuda_runtime.h>
#include <math_constants.h>

#define N 512
#define D 128
#define NT 16              // 512/32 tiles per side
#define MARGIN 0.3f
#define PAD 132            // 128 + 4 floats row pad (keeps 16B alignment, tames conflicts)

__device__ float g_dist[N * N];
__device__ double g_sum;
__device__ unsigned long long g_cnt;

// ---------------------------------------------------------------------------
// Kernel 1: pairwise distances via ||xi||^2 + ||xj||^2 - 2 xi.xj  (the same
// identity the reference uses). Upper-triangle tiles only; each block computes
// a 32x32 tile and writes it to both d and d^T. 2x2 register tile per thread.
// ---------------------------------------------------------------------------
__global__ __launch_bounds__(256) void dist_kernel(const float* __restrict__ x) {
    __shared__ __align__(16) float Xi[32][PAD];
    __shared__ __align__(16) float Xj[32][PAD];
    __shared__ float sni[32], snj[32];

    const int tid = threadIdx.x;

    if (blockIdx.x == 0 && tid == 0) { g_sum = 0.0; g_cnt = 0ull; }

    // decode linear block -> (bi, bj) with bi <= bj (136 blocks total)
    int b = blockIdx.x, bi = 0;
    while (b >= NT - bi) { b -= NT - bi; bi++; }
    const int bj = bi + b;
    const int i0 = bi * 32, j0 = bj * 32;

    // Stage both tiles; warp w's 32 lanes cover exactly one row per chunk,
    // so row norms come from a warp shuffle reduction for free.
    const float4* gx = reinterpret_cast<const float4*>(x);
    const int lane = tid & 31;
#pragma unroll
    for (int k = 0; k < 4; k++) {
        int f  = tid + k * 256;           // 0..1023
        int r  = f >> 5;                  // row in tile
        int c4 = f & 31;                  // float4 column
        float4 v = gx[(i0 + r) * 32 + c4];
        *reinterpret_cast<float4*>(&Xi[r][c4 * 4]) = v;
        float ps = fmaf(v.x, v.x, fmaf(v.y, v.y, fmaf(v.z, v.z, v.w * v.w)));
#pragma unroll
        for (int off = 16; off; off >>= 1) ps += __shfl_down_sync(0xffffffffu, ps, off);
        if (lane == 0) sni[r] = ps;

        float4 w = gx[(j0 + r) * 32 + c4];
        *reinterpret_cast<float4*>(&Xj[r][c4 * 4]) = w;
        float qs = fmaf(w.x, w.x, fmaf(w.y, w.y, fmaf(w.z, w.z, w.w * w.w)));
#pragma unroll
        for (int off = 16; off; off >>= 1) qs += __shfl_down_sync(0xffffffffu, qs, off);
        if (lane == 0) snj[r] = qs;
    }
    __syncthreads();

    const int tx = tid & 15, ty = tid >> 4;
    float acc00 = 0.f, acc01 = 0.f, acc10 = 0.f, acc11 = 0.f;

#pragma unroll 4
    for (int c4 = 0; c4 < 32; c4++) {
        float4 a0 = *reinterpret_cast<const float4*>(&Xi[2 * ty    ][c4 * 4]);
        float4 a1 = *reinterpret_cast<const float4*>(&Xi[2 * ty + 1][c4 * 4]);
        float4 b0 = *reinterpret_cast<const float4*>(&Xj[2 * tx    ][c4 * 4]);
        float4 b1 = *reinterpret_cast<const float4*>(&Xj[2 * tx + 1][c4 * 4]);
        acc00 = fmaf(a0.x, b0.x, fmaf(a0.y, b0.y, fmaf(a0.z, b0.z, fmaf(a0.w, b0.w, acc00))));
        acc01 = fmaf(a0.x, b1.x, fmaf(a0.y, b1.y, fmaf(a0.z, b1.z, fmaf(a0.w, b1.w, acc01))));
        acc10 = fmaf(a1.x, b0.x, fmaf(a1.y, b0.y, fmaf(a1.z, b0.z, fmaf(a1.w, b0.w, acc10))));
        acc11 = fmaf(a1.x, b1.x, fmaf(a1.y, b1.y, fmaf(a1.z, b1.z, fmaf(a1.w, b1.w, acc11))));
    }

    const int gi = i0 + 2 * ty, gj = j0 + 2 * tx;
    const float ni0 = sni[2 * ty], ni1 = sni[2 * ty + 1];
    const float nj0 = snj[2 * tx], nj1 = snj[2 * tx + 1];

    float d00 = sqrtf(fmaxf(fmaf(-2.f, acc00, ni0 + nj0), 0.f));
    float d01 = sqrtf(fmaxf(fmaf(-2.f, acc01, ni0 + nj1), 0.f));
    float d10 = sqrtf(fmaxf(fmaf(-2.f, acc10, ni1 + nj0), 0.f));
    float d11 = sqrtf(fmaxf(fmaf(-2.f, acc11, ni1 + nj1), 0.f));

    g_dist[ gi      * N + gj    ] = d00;  g_dist[ gj      * N + gi    ] = d00;
    g_dist[ gi      * N + gj + 1] = d01;  g_dist[(gj + 1) * N + gi    ] = d01;
    g_dist[(gi + 1) * N + gj    ] = d10;  g_dist[ gj      * N + gi + 1] = d10;
    g_dist[(gi + 1) * N + gj + 1] = d11;  g_dist[(gj + 1) * N + gi + 1] = d11;
}

// ---------------------------------------------------------------------------
// Kernel 2: per-anchor triplet hinge. Positives are compacted into a short
// list first (~10 entries), so the hot loop runs ~10 iterations, not 512.
// ---------------------------------------------------------------------------
__global__ __launch_bounds__(256) void triplet_kernel(const int* __restrict__ labels) {
    __shared__ float drow[N];
    __shared__ int   slbl[N];
    __shared__ int   plist[128];
    __shared__ int   pcount;
    __shared__ float red_s[8];
    __shared__ unsigned red_c[8];

    const int i   = blockIdx.x;
    const int tid = threadIdx.x;

    if (tid == 0) pcount = 0;
    for (int t = tid; t < N; t += 256) {
        drow[t] = g_dist[i * N + t];
        slbl[t] = labels[t];
    }
    __syncthreads();

    const int li = slbl[i];

    // compact positive-j list
#pragma unroll
    for (int k = 0; k < 2; k++) {
        int j = tid + k * 256;
        if (slbl[j] == li && j != i) {
            int p = atomicAdd(&pcount, 1);
            plist[p] = j;
        }
    }
    const float nk0 = (slbl[tid]       != li) ? drow[tid]       : CUDART_INF_F;
    const float nk1 = (slbl[tid + 256] != li) ? drow[tid + 256] : CUDART_INF_F;
    __syncthreads();

    const int np = pcount;
    float sum = 0.f;
    unsigned cnt = 0;

    for (int p = 0; p < np; p++) {
        const float apm = drow[plist[p]] + MARGIN;
        const float v0 = apm - nk0;
        const float v1 = apm - nk1;
        if (v0 > 0.f) { sum += v0; cnt += (v0 > 1e-16f); }
        if (v1 > 0.f) { sum += v1; cnt += (v1 > 1e-16f); }
    }

#pragma unroll
    for (int off = 16; off; off >>= 1) {
        sum += __shfl_down_sync(0xffffffffu, sum, off);
        cnt += __shfl_down_sync(0xffffffffu, cnt, off);
    }
    if ((tid & 31) == 0) { red_s[tid >> 5] = sum; red_c[tid >> 5] = cnt; }
    __syncthreads();
    if (tid < 8) {
        sum = red_s[tid];
        cnt = red_c[tid];
#pragma unroll
        for (int off = 4; off; off >>= 1) {
            sum += __shfl_down_sync(0xffu, sum, off);
            cnt += __shfl_down_sync(0xffu, cnt, off);
        }
        if (tid == 0) {
            atomicAdd(&g_sum, (double)sum);
            atomicAdd(&g_cnt, (unsigned long long)cnt);
        }
    }
}

__global__ void finalize_kernel(float* __restrict__ out) {
    out[0] = (float)(g_sum / ((double)g_cnt + 1e-16));
}

extern "C" void kernel_launch(void* const* d_in, const int* in_sizes, int n_in,
                              void* d_out, int out_size) {
    const float* emb    = (const float*)d_in[0];   // [512, 128] fp32
    const int*   labels = (const int*)d_in[1];     // [512] int32
    float*       out    = (float*)d_out;

    dist_kernel<<<NT * (NT + 1) / 2, 256>>>(emb);  // 136 blocks, upper triangle
    triplet_kernel<<<N, 256>>>(labels);
    finalize_kernel<<<1, 1>>>(out);
}

// round 5
// speedup vs baseline: 3.0280x; 1.0129x over previous
#include <cuda_runtime.h>
#include <math_constants.h>

#define N 512
#define MARGIN 0.3f
#define NB 256             // 32 row-tiles x 8 col-tiles
#define NTHR 128
#define TR 16              // tile rows (anchors)
#define TC 64              // tile cols
#define PADF 132           // floats per smem row (4-float pad -> 8 bank-group spread)

__device__ float g_dist[N * N];
__device__ double g_sum;
__device__ unsigned long long g_cnt;
__device__ unsigned g_arrive;   // zero-init; reset by last block each launch
__device__ unsigned g_done;

__global__ __launch_bounds__(NTHR) void fused_kernel(
    const float* __restrict__ x,
    const int* __restrict__ labels,
    float* __restrict__ out)
{
    __shared__ __align__(16) float Xj[TC][PADF];     // 33792 B
    __shared__ __align__(16) union SU {
        float Xi[TR][PADF];                          // 8448 B (phase 1)
        struct {
            float drow[N];
            int   slbl[N];
            int   plist[96];
            int   pcount;
            float red_s[4];
            unsigned red_c[4];
        } p2;                                        // (phase 2)
    } u;
    __shared__ float sni[TR], snj[TC];

    const int tid  = threadIdx.x;
    const int lane = tid & 31;
    const int w    = tid >> 5;

    if (blockIdx.x == 0 && tid == 0) { g_sum = 0.0; g_cnt = 0ull; }

    // ======================= Phase 1: distance tile =======================
    const int i0 = (blockIdx.x >> 3) * TR;
    const int j0 = (blockIdx.x & 7)  * TC;
    const float4* gx = reinterpret_cast<const float4*>(x);

    // Stage Xi (16 rows): each (k, warp) covers exactly one row; norm via shuffle.
#pragma unroll
    for (int k = 0; k < 4; k++) {
        const int r = 4 * k + w;
        float4 v = gx[(i0 + r) * 32 + lane];
        *reinterpret_cast<float4*>(&u.Xi[r][lane * 4]) = v;
        float ps = fmaf(v.x, v.x, fmaf(v.y, v.y, fmaf(v.z, v.z, v.w * v.w)));
#pragma unroll
        for (int off = 16; off; off >>= 1) ps += __shfl_down_sync(0xffffffffu, ps, off);
        if (lane == 0) sni[r] = ps;
    }
    // Stage Xj (64 rows)
#pragma unroll
    for (int k = 0; k < 16; k++) {
        const int r = 4 * k + w;
        float4 v = gx[(j0 + r) * 32 + lane];
        *reinterpret_cast<float4*>(&Xj[r][lane * 4]) = v;
        float ps = fmaf(v.x, v.x, fmaf(v.y, v.y, fmaf(v.z, v.z, v.w * v.w)));
#pragma unroll
        for (int off = 16; off; off >>= 1) ps += __shfl_down_sync(0xffffffffu, ps, off);
        if (lane == 0) snj[r] = ps;
    }
    __syncthreads();

    // 2x4 register tile: rows {2ty, 2ty+1}, cols {tx, tx+16, tx+32, tx+48}
    const int tx = tid & 15, ty = tid >> 4;
    const int r0 = 2 * ty;
    float a0c0 = 0.f, a0c1 = 0.f, a0c2 = 0.f, a0c3 = 0.f;
    float a1c0 = 0.f, a1c1 = 0.f, a1c2 = 0.f, a1c3 = 0.f;

#pragma unroll
    for (int c4 = 0; c4 < 32; c4++) {
        float4 a0 = *reinterpret_cast<const float4*>(&u.Xi[r0    ][c4 * 4]);
        float4 a1 = *reinterpret_cast<const float4*>(&u.Xi[r0 + 1][c4 * 4]);
        float4 b0 = *reinterpret_cast<const float4*>(&Xj[tx     ][c4 * 4]);
        float4 b1 = *reinterpret_cast<const float4*>(&Xj[tx + 16][c4 * 4]);
        float4 b2 = *reinterpret_cast<const float4*>(&Xj[tx + 32][c4 * 4]);
        float4 b3 = *reinterpret_cast<const float4*>(&Xj[tx + 48][c4 * 4]);
        a0c0 = fmaf(a0.x,b0.x, fmaf(a0.y,b0.y, fmaf(a0.z,b0.z, fmaf(a0.w,b0.w, a0c0))));
        a0c1 = fmaf(a0.x,b1.x, fmaf(a0.y,b1.y, fmaf(a0.z,b1.z, fmaf(a0.w,b1.w, a0c1))));
        a0c2 = fmaf(a0.x,b2.x, fmaf(a0.y,b2.y, fmaf(a0.z,b2.z, fmaf(a0.w,b2.w, a0c2))));
        a0c3 = fmaf(a0.x,b3.x, fmaf(a0.y,b3.y, fmaf(a0.z,b3.z, fmaf(a0.w,b3.w, a0c3))));
        a1c0 = fmaf(a1.x,b0.x, fmaf(a1.y,b0.y, fmaf(a1.z,b0.z, fmaf(a1.w,b0.w, a1c0))));
        a1c1 = fmaf(a1.x,b1.x, fmaf(a1.y,b1.y, fmaf(a1.z,b1.z, fmaf(a1.w,b1.w, a1c1))));
        a1c2 = fmaf(a1.x,b2.x, fmaf(a1.y,b2.y, fmaf(a1.z,b2.z, fmaf(a1.w,b2.w, a1c2))));
        a1c3 = fmaf(a1.x,b3.x, fmaf(a1.y,b3.y, fmaf(a1.z,b3.z, fmaf(a1.w,b3.w, a1c3))));
    }

    {
        const float ni0 = sni[r0], ni1 = sni[r0 + 1];
        float accs[2][4] = {{a0c0,a0c1,a0c2,a0c3},{a1c0,a1c1,a1c2,a1c3}};
#pragma unroll
        for (int rr = 0; rr < 2; rr++) {
            const float ni = rr ? ni1 : ni0;
            float* dst = g_dist + (i0 + r0 + rr) * N + j0;
#pragma unroll
            for (int c = 0; c < 4; c++) {
                const int col = tx + 16 * c;
                float sq = fmaf(-2.f, accs[rr][c], ni + snj[col]);
                dst[col] = sqrtf(fmaxf(sq, 0.f));
            }
        }
    }

    // ======================= Grid-wide sync =======================
    __syncthreads();
    __threadfence();
    if (tid == 0) {
        atomicAdd(&g_arrive, 1u);
        while (*((volatile unsigned*)&g_arrive) < NB) __nanosleep(32);
    }
    __syncthreads();

    // ======================= Phase 2: triplet hinge (2 anchors/block) =====
    {
        int4 lv = reinterpret_cast<const int4*>(labels)[tid];
        *reinterpret_cast<int4*>(&u.p2.slbl[tid * 4]) = lv;
    }
    __syncthreads();

    for (int a = 2 * blockIdx.x; a < 2 * blockIdx.x + 2; a++) {
        float4 dv = reinterpret_cast<const float4*>(g_dist + a * N)[tid];
        *reinterpret_cast<float4*>(&u.p2.drow[tid * 4]) = dv;
        if (tid == 0) u.p2.pcount = 0;
        __syncthreads();

        const int li = u.p2.slbl[a];
        float nk[4];
#pragma unroll
        for (int m = 0; m < 4; m++) {
            const int j  = tid + 128 * m;
            const int lj = u.p2.slbl[j];
            nk[m] = (lj != li) ? u.p2.drow[j] : CUDART_INF_F;
            if (lj == li && j != a) {
                int p = atomicAdd(&u.p2.pcount, 1);
                u.p2.plist[p] = j;
            }
        }
        __syncthreads();

        const int np = u.p2.pcount;
        float sum = 0.f;
        unsigned cnt = 0;
        for (int p = 0; p < np; p++) {
            const float apm = u.p2.drow[u.p2.plist[p]] + MARGIN;
#pragma unroll
            for (int m = 0; m < 4; m++) {
                const float v = apm - nk[m];
                if (v > 0.f) { sum += v; cnt += (v > 1e-16f); }
            }
        }

#pragma unroll
        for (int off = 16; off; off >>= 1) {
            sum += __shfl_down_sync(0xffffffffu, sum, off);
            cnt += __shfl_down_sync(0xffffffffu, cnt, off);
        }
        if (lane == 0) { u.p2.red_s[w] = sum; u.p2.red_c[w] = cnt; }
        __syncthreads();
        if (tid == 0) {
            float s = u.p2.red_s[0] + u.p2.red_s[1] + u.p2.red_s[2] + u.p2.red_s[3];
            unsigned c = u.p2.red_c[0] + u.p2.red_c[1] + u.p2.red_c[2] + u.p2.red_c[3];
            atomicAdd(&g_sum, (double)s);
            atomicAdd(&g_cnt, (unsigned long long)c);
        }
        __syncthreads();
    }

    // ======================= Finalize: last block =======================
    __threadfence();
    if (tid == 0) {
        unsigned t = atomicAdd(&g_done, 1u);
        if (t == NB - 1) {
            double s = atomicAdd(&g_sum, 0.0);
            unsigned long long c = atomicAdd(&g_cnt, 0ull);
            out[0] = (float)(s / ((double)c + 1e-16));
            g_arrive = 0;            // reset for next graph replay
            g_done = 0;
            __threadfence();
        }
    }
}

extern "C" void kernel_launch(void* const* d_in, const int* in_sizes, int n_in,
                              void* d_out, int out_size) {
    const float* emb    = (const float*)d_in[0];   // [512, 128] fp32
    const int*   labels = (const int*)d_in[1];     // [512] int32
    float*       out    = (float*)d_out;

    fused_kernel<<<NB, NTHR>>>(emb, labels, out);
}